// round 14
// baseline (speedup 1.0000x reference)
#include <cuda_runtime.h>

#define BB 2048
#define LL 256
#define FF 64
#define HH 32
#define G4 256   // 4*F

// Scratch (device globals; no allocation allowed)
__device__ float d_A[BB * G4];     // per-batch input bias
__device__ float d_E[2 * G4];      // per-token embedding projection
__device__ float d_h0[BB * FF];
__device__ float d_c0[BB * FF];
__device__ float d_Y[BB * FF * LL];  // streamed h, layout [b][f][t]

typedef unsigned long long u64;

__device__ __forceinline__ u64 pack2(float lo, float hi) {
    u64 r; asm("mov.b64 %0, {%1,%2};" : "=l"(r) : "f"(lo), "f"(hi)); return r;
}
__device__ __forceinline__ void fma2(u64 &d, u64 a, u64 b) {
    asm("fma.rn.f32x2 %0, %1, %2, %0;" : "+l"(d) : "l"(a), "l"(b));
}
__device__ __forceinline__ float sum2(u64 v) {
    float lo, hi; asm("mov.b64 {%0,%1}, %2;" : "=f"(lo), "=f"(hi) : "l"(v));
    return lo + hi;
}
// MUFU.TANH — accuracy proven (rel_err ~1e-7)
__device__ __forceinline__ float tanh_mufu(float x) {
    float y; asm("tanh.approx.f32 %0, %1;" : "=f"(y) : "f"(x)); return y;
}

// ---------------------------------------------------------------------------
// Kernel 1: precompute A[b], E[k], h0[b], c0[b]  (proven; clock canary 19.5us)
// ---------------------------------------------------------------------------
__global__ void precompute_kernel(
    const float* __restrict__ g,
    const float* __restrict__ W_emb,  const float* __restrict__ b_emb,
    const float* __restrict__ W_g1,   const float* __restrict__ b_g1,
    const float* __restrict__ W_g2,   const float* __restrict__ b_g2,
    const float* __restrict__ W_gh,   const float* __restrict__ b_gh,
    const float* __restrict__ W_gc,   const float* __restrict__ b_gc,
    const float* __restrict__ Wi,     const float* __restrict__ b_lstm)
{
    int b = blockIdx.x;
    int j = threadIdx.x;
    __shared__ float sh_t[HH];
    __shared__ float sh_gv[FF];

    float gb = g[b];
    if (j < HH) sh_t[j] = tanhf(gb * W_g1[j] + b_g1[j]);
    __syncthreads();
    if (j < FF) {
        float acc = b_g2[j];
        #pragma unroll 8
        for (int h = 0; h < HH; h++) acc += sh_t[h] * W_g2[h * FF + j];
        sh_gv[j] = acc;
        d_h0[b * FF + j] = gb * W_gh[j] + b_gh[j];
        d_c0[b * FF + j] = gb * W_gc[j] + b_gc[j];
    }
    __syncthreads();
    float acc = b_lstm[j];
    #pragma unroll 8
    for (int f = 0; f < FF; f++) acc += (b_emb[f] + sh_gv[f]) * Wi[f * G4 + j];
    d_A[b * G4 + j] = acc;

    if (b == 0) {
        float e0 = 0.f, e1 = 0.f;
        #pragma unroll 8
        for (int f = 0; f < FF; f++) {
            float wi = Wi[f * G4 + j];
            e0 += W_emb[f] * wi;
            e1 += W_emb[FF + f] * wi;
        }
        d_E[j] = e0;
        d_E[G4 + j] = e1;
    }
}

// ---------------------------------------------------------------------------
// Kernel 2: LSTM recurrence — R13 structure (G=2, 256 threads, one barrier,
// MUFU gates) with a K-SPLIT matvec: lane (g,q) loads ONLY h-quarter
// [16q,16q+16) (8 LDS.128 total vs 32) and computes partials of ALL 4 gate
// columns of feature g over that quarter (same 64 weight regs, re-indexed;
// same 64 FMA2). A 2-round butterfly (6 shfl) reduces quarters so lane q
// ends with gate q's full z. Downstream (act/gather/c/h/store) unchanged.
// ---------------------------------------------------------------------------
__global__ void __launch_bounds__(256, 2) lstm_kernel(
    const int*   __restrict__ s,      // (B, L)
    const float* __restrict__ Wh)     // (64, 256)
{
    int b0   = 2 * blockIdx.x;
    int b1   = b0 + 1;
    int tid  = threadIdx.x;
    int g    = tid >> 2;        // feature 0..63
    int q    = tid & 3;         // gate owned AND K-quarter loaded
    int col  = q * FF + g;      // gate column in [0,256)
    int lane = tid & 31;
    int q1   = q & 1;
    int q2   = q & 2;

    __shared__ __align__(16) float sh_h[2][2][FF];   // [batch][parity][feat]
    __shared__ int sh_tok[2][LL];

    // Weights: w2[j*8 + k2] = (Wh[16q+2k2][j*64+g], Wh[16q+2k2+1][j*64+g])
    // (rows of MY K-quarter, columns = all 4 gates of feature g)
    u64 w2[32];
    #pragma unroll
    for (int j = 0; j < 4; j++)
        #pragma unroll
        for (int k2 = 0; k2 < 8; k2++) {
            int row = 16 * q + 2 * k2;
            int cj  = j * FF + g;
            w2[j * 8 + k2] = pack2(Wh[row * G4 + cj], Wh[(row + 1) * G4 + cj]);
        }

    float e0 = d_E[col];
    float ed = d_E[G4 + col] - e0;
    float xb0  = d_A[b0 * G4 + col] + e0;
    float xb1  = d_A[b1 * G4 + col] + e0;
    float xb0e = xb0 + ed;
    float xb1e = xb1 + ed;

    // uniform activation constants: q==2 -> tanh, else sigmoid
    float aA = (q == 2) ? 1.f : 0.5f;
    float aB = aA;
    float aC = (q == 2) ? 0.f : 0.5f;

    sh_tok[0][tid] = s[b0 * LL + tid];
    sh_tok[1][tid] = s[b1 * LL + tid];
    if (tid < FF) {
        sh_h[0][0][tid] = d_h0[b0 * FF + tid];
        sh_h[1][0][tid] = d_h0[b1 * FF + tid];
    }
    float c0 = d_c0[b0 * FF + g];
    float c1 = d_c0[b1 * FF + g];
    float* y0 = d_Y + (b0 * FF + g) * LL;   // [b][f][t] layout
    float* y1 = d_Y + (b1 * FF + g) * LL;
    float h0prev = 0.f, h1prev = 0.f;
    __syncthreads();

    #pragma unroll 2
    for (int u = 0; u < LL; u++) {
        int p = u & 1;

        int t0 = (u == 0) ? 0 : sh_tok[0][u - 1];
        int t1 = (u == 0) ? 0 : sh_tok[1][u - 1];
        float x0 = t0 ? xb0e : xb0;
        float x1 = t1 ? xb1e : xb1;

        // quarter-matvec: partials of all 4 gate columns over rows
        // [16q, 16q+16), both batches. 4 LDS.128 per batch.
        const ulonglong2* hA = ((const ulonglong2*)sh_h[0][p]) + 4 * q;
        const ulonglong2* hB = ((const ulonglong2*)sh_h[1][p]) + 4 * q;
        u64 acc0[4] = {0ull, 0ull, 0ull, 0ull};
        u64 acc1[4] = {0ull, 0ull, 0ull, 0ull};
        #pragma unroll
        for (int k = 0; k < 4; k++) {
            ulonglong2 ha = hA[k];   // floats 16q+4k .. 16q+4k+3 (batch0)
            ulonglong2 ga = hB[k];   // same rows, batch1
            #pragma unroll
            for (int j = 0; j < 4; j++) {
                fma2(acc0[j], ha.x, w2[j * 8 + 2 * k + 0]);
                fma2(acc0[j], ha.y, w2[j * 8 + 2 * k + 1]);
                fma2(acc1[j], ga.x, w2[j * 8 + 2 * k + 0]);
                fma2(acc1[j], ga.y, w2[j * 8 + 2 * k + 1]);
            }
        }
        float p00 = sum2(acc0[0]), p01 = sum2(acc0[1]);
        float p02 = sum2(acc0[2]), p03 = sum2(acc0[3]);
        float p10 = sum2(acc1[0]), p11 = sum2(acc1[1]);
        float p12 = sum2(acc1[2]), p13 = sum2(acc1[3]);

        // butterfly round 1 (xor 1): exchange the gates whose bit0 != q&1
        float v0a = q1 ? p00 : p01;          // send: gate with bit0 != q1
        float v0b = q1 ? p02 : p03;
        float v1a = q1 ? p10 : p11;
        float v1b = q1 ? p12 : p13;
        float r0a = __shfl_xor_sync(0xffffffffu, v0a, 1);
        float r0b = __shfl_xor_sync(0xffffffffu, v0b, 1);
        float r1a = __shfl_xor_sync(0xffffffffu, v1a, 1);
        float r1b = __shfl_xor_sync(0xffffffffu, v1b, 1);
        float A0 = (q1 ? p01 : p00) + r0a;   // gate bit0==q1, bit1==0
        float B0 = (q1 ? p03 : p02) + r0b;   // gate bit0==q1, bit1==1
        float A1 = (q1 ? p11 : p10) + r1a;
        float B1 = (q1 ? p13 : p12) + r1b;

        // butterfly round 2 (xor 2)
        float w0 = q2 ? A0 : B0;             // send: gate with bit1 != q&2
        float w1 = q2 ? A1 : B1;
        float s0 = __shfl_xor_sync(0xffffffffu, w0, 2);
        float s1 = __shfl_xor_sync(0xffffffffu, w1, 2);
        float z0 = x0 + (q2 ? B0 : A0) + s0; // own gate q, full K
        float z1 = x1 + (q2 ? B1 : A1) + s1;

        // uniform activation of OWN gate, then gather the 4 gates
        float act0 = fmaf(tanh_mufu(aA * z0), aB, aC);
        float act1 = fmaf(tanh_mufu(aA * z1), aB, aC);
        int lb = lane & ~3;
        float ai0 = __shfl_sync(0xffffffffu, act0, lb + 0);
        float ai1 = __shfl_sync(0xffffffffu, act1, lb + 0);
        float af0 = __shfl_sync(0xffffffffu, act0, lb + 1);
        float af1 = __shfl_sync(0xffffffffu, act1, lb + 1);
        float ag0 = __shfl_sync(0xffffffffu, act0, lb + 2);
        float ag1 = __shfl_sync(0xffffffffu, act1, lb + 2);
        float ao0 = __shfl_sync(0xffffffffu, act0, lb + 3);
        float ao1 = __shfl_sync(0xffffffffu, act1, lb + 3);

        c0 = af0 * c0 + ai0 * ag0;
        c1 = af1 * c1 + ai1 * ag1;
        float h0 = ao0 * tanh_mufu(c0);
        float h1 = ao1 * tanh_mufu(c1);
        if (q == 0) {
            sh_h[0][p ^ 1][g] = h0;
            sh_h[1][p ^ 1][g] = h1;
            if (p) {   // odd step: flush (h(u-1), h(u)) as one float2
                *(float2*)(y0 + (u - 1)) = make_float2(h0prev, h0);
                *(float2*)(y1 + (u - 1)) = make_float2(h1prev, h1);
            }
        }
        h0prev = h0;
        h1prev = h1;
        __syncthreads();
    }
}

// ---------------------------------------------------------------------------
// Kernel 3: epilogue — logits, log-softmax, per-batch token-logp sum.
// grid = B, block = 256 (thread t owns timestep t). d_Y layout [b][f][t].
// ---------------------------------------------------------------------------
__global__ void __launch_bounds__(256) logit_kernel(
    const int*   __restrict__ s,      // (B, L)
    const float* __restrict__ W_amp,  // (64, 2)
    const float* __restrict__ b_amp,  // (2)
    float* __restrict__ out)          // (B,)
{
    int b = blockIdx.x;
    int t = threadIdx.x;
    int lane = t & 31;
    int warp = t >> 5;

    __shared__ __align__(16) float sw[2 * FF];  // W_amp
    __shared__ float red[8];
    if (t < 2 * FF) sw[t] = W_amp[t];
    __syncthreads();

    const float* yb = d_Y + b * FF * LL + t;
    float l0 = b_amp[0], l1 = b_amp[1];
    #pragma unroll 8
    for (int f = 0; f < FF; f++) {
        float v = yb[f * LL];
        l0 += v * sw[2 * f + 0];
        l1 += v * sw[2 * f + 1];
    }
    int tok = s[b * LL + t];
    float m = fmaxf(l0, l1);
    float lse = m + __logf(__expf(l0 - m) + __expf(l1 - m));
    float lp = (tok ? l1 : l0) - lse;

    #pragma unroll
    for (int o = 16; o > 0; o >>= 1)
        lp += __shfl_down_sync(0xffffffffu, lp, o);
    if (lane == 0) red[warp] = lp;
    __syncthreads();
    if (warp == 0) {
        float v = (lane < 8) ? red[lane] : 0.f;
        #pragma unroll
        for (int o = 4; o > 0; o >>= 1)
            v += __shfl_down_sync(0xffffffffu, v, o);
        if (lane == 0) out[b] = v;
    }
}

// ---------------------------------------------------------------------------
// Launch. Input order:
// 0:s 1:g 2:W_emb 3:b_emb 4:W_g1 5:b_g1 6:W_g2 7:b_g2 8:W_gh 9:b_gh
// 10:W_gc 11:b_gc 12:Wi 13:Wh 14:b_lstm 15:W_amp 16:b_amp
// ---------------------------------------------------------------------------
extern "C" void kernel_launch(void* const* d_in, const int* in_sizes, int n_in,
                              void* d_out, int out_size) {
    const int*   s      = (const int*)  d_in[0];
    const float* g      = (const float*)d_in[1];
    const float* W_emb  = (const float*)d_in[2];
    const float* b_emb  = (const float*)d_in[3];
    const float* W_g1   = (const float*)d_in[4];
    const float* b_g1   = (const float*)d_in[5];
    const float* W_g2   = (const float*)d_in[6];
    const float* b_g2   = (const float*)d_in[7];
    const float* W_gh   = (const float*)d_in[8];
    const float* b_gh   = (const float*)d_in[9];
    const float* W_gc   = (const float*)d_in[10];
    const float* b_gc   = (const float*)d_in[11];
    const float* Wi     = (const float*)d_in[12];
    const float* Wh     = (const float*)d_in[13];
    const float* b_lstm = (const float*)d_in[14];
    const float* W_amp  = (const float*)d_in[15];
    const float* b_amp  = (const float*)d_in[16];
    float* out = (float*)d_out;

    precompute_kernel<<<BB, 256>>>(g, W_emb, b_emb, W_g1, b_g1, W_g2, b_g2,
                                   W_gh, b_gh, W_gc, b_gc, Wi, b_lstm);
    lstm_kernel<<<BB / 2, 256>>>(s, Wh);
    logit_kernel<<<BB, 256>>>(s, W_amp, b_amp, out);
}

// round 15
// speedup vs baseline: 1.0759x; 1.0759x over previous
#include <cuda_runtime.h>

#define BB 2048
#define LL 256
#define FF 64
#define HH 32
#define G4 256   // 4*F

// Scratch (device globals; no allocation allowed)
__device__ float d_A[BB * G4];     // per-batch input bias
__device__ float d_E[2 * G4];      // per-token embedding projection
__device__ float d_h0[BB * FF];
__device__ float d_c0[BB * FF];
__device__ float d_Y[BB * FF * LL];  // streamed h, layout [b][f][t]

typedef unsigned long long u64;

__device__ __forceinline__ u64 pack2(float lo, float hi) {
    u64 r; asm("mov.b64 %0, {%1,%2};" : "=l"(r) : "f"(lo), "f"(hi)); return r;
}
__device__ __forceinline__ void fma2(u64 &d, u64 a, u64 b) {
    asm("fma.rn.f32x2 %0, %1, %2, %0;" : "+l"(d) : "l"(a), "l"(b));
}
__device__ __forceinline__ u64 add2(u64 a, u64 b) {
    u64 r; asm("add.rn.f32x2 %0, %1, %2;" : "=l"(r) : "l"(a), "l"(b)); return r;
}
__device__ __forceinline__ float sum2(u64 v) {
    float lo, hi; asm("mov.b64 {%0,%1}, %2;" : "=f"(lo), "=f"(hi) : "l"(v));
    return lo + hi;
}
// MUFU.TANH — accuracy proven (rel_err ~1e-7)
__device__ __forceinline__ float tanh_mufu(float x) {
    float y; asm("tanh.approx.f32 %0, %1;" : "=f"(y) : "f"(x)); return y;
}

// ---------------------------------------------------------------------------
// Kernel 1: precompute A[b], E[k], h0[b], c0[b]  (proven; clock canary 19.5us)
// ---------------------------------------------------------------------------
__global__ void precompute_kernel(
    const float* __restrict__ g,
    const float* __restrict__ W_emb,  const float* __restrict__ b_emb,
    const float* __restrict__ W_g1,   const float* __restrict__ b_g1,
    const float* __restrict__ W_g2,   const float* __restrict__ b_g2,
    const float* __restrict__ W_gh,   const float* __restrict__ b_gh,
    const float* __restrict__ W_gc,   const float* __restrict__ b_gc,
    const float* __restrict__ Wi,     const float* __restrict__ b_lstm)
{
    int b = blockIdx.x;
    int j = threadIdx.x;
    __shared__ float sh_t[HH];
    __shared__ float sh_gv[FF];

    float gb = g[b];
    if (j < HH) sh_t[j] = tanhf(gb * W_g1[j] + b_g1[j]);
    __syncthreads();
    if (j < FF) {
        float acc = b_g2[j];
        #pragma unroll 8
        for (int h = 0; h < HH; h++) acc += sh_t[h] * W_g2[h * FF + j];
        sh_gv[j] = acc;
        d_h0[b * FF + j] = gb * W_gh[j] + b_gh[j];
        d_c0[b * FF + j] = gb * W_gc[j] + b_gc[j];
    }
    __syncthreads();
    float acc = b_lstm[j];
    #pragma unroll 8
    for (int f = 0; f < FF; f++) acc += (b_emb[f] + sh_gv[f]) * Wi[f * G4 + j];
    d_A[b * G4 + j] = acc;

    if (b == 0) {
        float e0 = 0.f, e1 = 0.f;
        #pragma unroll 8
        for (int f = 0; f < FF; f++) {
            float wi = Wi[f * G4 + j];
            e0 += W_emb[f] * wi;
            e1 += W_emb[FF + f] * wi;
        }
        d_E[j] = e0;
        d_E[G4 + j] = e1;
    }
}

// ---------------------------------------------------------------------------
// Kernel 2: LSTM recurrence — R11/R13 structure (G=2, 256 threads, one
// barrier, MUFU gates) with a K-HALF split + static partner:
// thread (g,q) loads ONLY h-half [32*(q&1), +32) -> 16 LDS.128/step (was 32),
// computes partials for its own column AND partner's column (lane^1 = gate
// q^1) over that half. Same 64 weight regs, same 64 FMA2. Combine = 2
// shfl_xor + 2 adds, no selects. Downstream unchanged from R13.
// ---------------------------------------------------------------------------
__global__ void __launch_bounds__(256, 2) lstm_kernel(
    const int*   __restrict__ s,      // (B, L)
    const float* __restrict__ Wh)     // (64, 256)
{
    int b0   = 2 * blockIdx.x;
    int b1   = b0 + 1;
    int tid  = threadIdx.x;
    int g    = tid >> 2;        // feature 0..63
    int q    = tid & 3;         // gate owned
    int col  = q * FF + g;      // own gate column
    int colp = (q ^ 1) * FF + g;// partner's gate column
    int hf   = q & 1;           // K-half loaded (== lane&1)
    int lane = tid & 31;

    __shared__ __align__(16) float sh_h[2][2][FF];   // [batch][parity][feat]
    __shared__ int sh_tok[2][LL];

    // Weights for MY K-half rows [32hf, 32hf+32):
    //   wo[j] = (Wh[32hf+2j][col],  Wh[32hf+2j+1][col])
    //   wp[j] = (Wh[32hf+2j][colp], Wh[32hf+2j+1][colp])
    u64 wo[16], wp[16];
    #pragma unroll
    for (int j = 0; j < 16; j++) {
        int row = 32 * hf + 2 * j;
        wo[j] = pack2(Wh[row * G4 + col],  Wh[(row + 1) * G4 + col]);
        wp[j] = pack2(Wh[row * G4 + colp], Wh[(row + 1) * G4 + colp]);
    }

    float e0 = d_E[col];
    float ed = d_E[G4 + col] - e0;
    float xb0  = d_A[b0 * G4 + col] + e0;
    float xb1  = d_A[b1 * G4 + col] + e0;
    float xb0e = xb0 + ed;
    float xb1e = xb1 + ed;

    // uniform activation constants: q==2 -> tanh, else sigmoid
    float aA = (q == 2) ? 1.f : 0.5f;
    float aB = aA;
    float aC = (q == 2) ? 0.f : 0.5f;

    sh_tok[0][tid] = s[b0 * LL + tid];
    sh_tok[1][tid] = s[b1 * LL + tid];
    if (tid < FF) {
        sh_h[0][0][tid] = d_h0[b0 * FF + tid];
        sh_h[1][0][tid] = d_h0[b1 * FF + tid];
    }
    float c0 = d_c0[b0 * FF + g];
    float c1 = d_c0[b1 * FF + g];
    float* y0 = d_Y + (b0 * FF + g) * LL;   // [b][f][t] layout
    float* y1 = d_Y + (b1 * FF + g) * LL;
    float h0prev = 0.f, h1prev = 0.f;
    __syncthreads();

    #pragma unroll 2
    for (int u = 0; u < LL; u++) {
        int p = u & 1;

        int t0 = (u == 0) ? 0 : sh_tok[0][u - 1];
        int t1 = (u == 0) ? 0 : sh_tok[1][u - 1];
        float x0 = t0 ? xb0e : xb0;
        float x1 = t1 ? xb1e : xb1;

        // half-matvec over rows [32hf, 32hf+32): 8 LDS.128 per batch.
        // Partials for own column and partner's column, both batches.
        const ulonglong2* hA = ((const ulonglong2*)sh_h[0][p]) + 8 * hf;
        const ulonglong2* hB = ((const ulonglong2*)sh_h[1][p]) + 8 * hf;
        u64 oa0 = 0ull, ob0 = 0ull, pa0 = 0ull, pb0 = 0ull;
        u64 oa1 = 0ull, ob1 = 0ull, pa1 = 0ull, pb1 = 0ull;
        #pragma unroll
        for (int k = 0; k < 4; k++) {
            ulonglong2 ha = hA[2 * k];       // local floats 8k .. 8k+3 (b0)
            ulonglong2 hb = hA[2 * k + 1];   // local floats 8k+4 .. 8k+7
            ulonglong2 ga = hB[2 * k];       // same rows, b1
            ulonglong2 gb = hB[2 * k + 1];
            fma2(oa0, ha.x, wo[4 * k + 0]);
            fma2(ob0, ha.y, wo[4 * k + 1]);
            fma2(oa0, hb.x, wo[4 * k + 2]);
            fma2(ob0, hb.y, wo[4 * k + 3]);
            fma2(pa0, ha.x, wp[4 * k + 0]);
            fma2(pb0, ha.y, wp[4 * k + 1]);
            fma2(pa0, hb.x, wp[4 * k + 2]);
            fma2(pb0, hb.y, wp[4 * k + 3]);
            fma2(oa1, ga.x, wo[4 * k + 0]);
            fma2(ob1, ga.y, wo[4 * k + 1]);
            fma2(oa1, gb.x, wo[4 * k + 2]);
            fma2(ob1, gb.y, wo[4 * k + 3]);
            fma2(pa1, ga.x, wp[4 * k + 0]);
            fma2(pb1, ga.y, wp[4 * k + 1]);
            fma2(pa1, gb.x, wp[4 * k + 2]);
            fma2(pb1, gb.y, wp[4 * k + 3]);
        }
        float own0 = sum2(add2(oa0, ob0));
        float par0 = sum2(add2(pa0, pb0));
        float own1 = sum2(add2(oa1, ob1));
        float par1 = sum2(add2(pa1, pb1));

        // exchange partner-column partials (partner = lane^1, static)
        float r0 = __shfl_xor_sync(0xffffffffu, par0, 1);
        float r1 = __shfl_xor_sync(0xffffffffu, par1, 1);
        float z0 = x0 + own0 + r0;
        float z1 = x1 + own1 + r1;

        // uniform activation of OWN gate, then gather the 4 gates
        float act0 = fmaf(tanh_mufu(aA * z0), aB, aC);
        float act1 = fmaf(tanh_mufu(aA * z1), aB, aC);
        int lb = lane & ~3;
        float ai0 = __shfl_sync(0xffffffffu, act0, lb + 0);
        float ai1 = __shfl_sync(0xffffffffu, act1, lb + 0);
        float af0 = __shfl_sync(0xffffffffu, act0, lb + 1);
        float af1 = __shfl_sync(0xffffffffu, act1, lb + 1);
        float ag0 = __shfl_sync(0xffffffffu, act0, lb + 2);
        float ag1 = __shfl_sync(0xffffffffu, act1, lb + 2);
        float ao0 = __shfl_sync(0xffffffffu, act0, lb + 3);
        float ao1 = __shfl_sync(0xffffffffu, act1, lb + 3);

        c0 = af0 * c0 + ai0 * ag0;
        c1 = af1 * c1 + ai1 * ag1;
        float h0 = ao0 * tanh_mufu(c0);
        float h1 = ao1 * tanh_mufu(c1);
        if (q == 0) {
            sh_h[0][p ^ 1][g] = h0;
            sh_h[1][p ^ 1][g] = h1;
            if (p) {   // odd step: flush (h(u-1), h(u)) as one float2
                *(float2*)(y0 + (u - 1)) = make_float2(h0prev, h0);
                *(float2*)(y1 + (u - 1)) = make_float2(h1prev, h1);
            }
        }
        h0prev = h0;
        h1prev = h1;
        __syncthreads();
    }
}

// ---------------------------------------------------------------------------
// Kernel 3: epilogue — logits, log-softmax, per-batch token-logp sum.
// grid = B, block = 256 (thread t owns timestep t). d_Y layout [b][f][t].
// ---------------------------------------------------------------------------
__global__ void __launch_bounds__(256) logit_kernel(
    const int*   __restrict__ s,      // (B, L)
    const float* __restrict__ W_amp,  // (64, 2)
    const float* __restrict__ b_amp,  // (2)
    float* __restrict__ out)          // (B,)
{
    int b = blockIdx.x;
    int t = threadIdx.x;
    int lane = t & 31;
    int warp = t >> 5;

    __shared__ __align__(16) float sw[2 * FF];  // W_amp
    __shared__ float red[8];
    if (t < 2 * FF) sw[t] = W_amp[t];
    __syncthreads();

    const float* yb = d_Y + b * FF * LL + t;
    float l0 = b_amp[0], l1 = b_amp[1];
    #pragma unroll 8
    for (int f = 0; f < FF; f++) {
        float v = yb[f * LL];
        l0 += v * sw[2 * f + 0];
        l1 += v * sw[2 * f + 1];
    }
    int tok = s[b * LL + t];
    float m = fmaxf(l0, l1);
    float lse = m + __logf(__expf(l0 - m) + __expf(l1 - m));
    float lp = (tok ? l1 : l0) - lse;

    #pragma unroll
    for (int o = 16; o > 0; o >>= 1)
        lp += __shfl_down_sync(0xffffffffu, lp, o);
    if (lane == 0) red[warp] = lp;
    __syncthreads();
    if (warp == 0) {
        float v = (lane < 8) ? red[lane] : 0.f;
        #pragma unroll
        for (int o = 4; o > 0; o >>= 1)
            v += __shfl_down_sync(0xffffffffu, v, o);
        if (lane == 0) out[b] = v;
    }
}

// ---------------------------------------------------------------------------
// Launch. Input order:
// 0:s 1:g 2:W_emb 3:b_emb 4:W_g1 5:b_g1 6:W_g2 7:b_g2 8:W_gh 9:b_gh
// 10:W_gc 11:b_gc 12:Wi 13:Wh 14:b_lstm 15:W_amp 16:b_amp
// ---------------------------------------------------------------------------
extern "C" void kernel_launch(void* const* d_in, const int* in_sizes, int n_in,
                              void* d_out, int out_size) {
    const int*   s      = (const int*)  d_in[0];
    const float* g      = (const float*)d_in[1];
    const float* W_emb  = (const float*)d_in[2];
    const float* b_emb  = (const float*)d_in[3];
    const float* W_g1   = (const float*)d_in[4];
    const float* b_g1   = (const float*)d_in[5];
    const float* W_g2   = (const float*)d_in[6];
    const float* b_g2   = (const float*)d_in[7];
    const float* W_gh   = (const float*)d_in[8];
    const float* b_gh   = (const float*)d_in[9];
    const float* W_gc   = (const float*)d_in[10];
    const float* b_gc   = (const float*)d_in[11];
    const float* Wi     = (const float*)d_in[12];
    const float* Wh     = (const float*)d_in[13];
    const float* b_lstm = (const float*)d_in[14];
    const float* W_amp  = (const float*)d_in[15];
    const float* b_amp  = (const float*)d_in[16];
    float* out = (float*)d_out;

    precompute_kernel<<<BB, 256>>>(g, W_emb, b_emb, W_g1, b_g1, W_g2, b_g2,
                                   W_gh, b_gh, W_gc, b_gc, Wi, b_lstm);
    lstm_kernel<<<BB / 2, 256>>>(s, Wh);
    logit_kernel<<<BB, 256>>>(s, W_amp, b_amp, out);
}

// round 17
// speedup vs baseline: 4.5364x; 4.2163x over previous
#include <cuda_runtime.h>
#include <cuda_fp16.h>

#define BB 2048
#define LL 256
#define FF 64
#define HH 32
#define G4 256   // 4*F
#define GB 16    // batches per CTA

// Scratch (device globals; no allocation allowed)
__device__ float d_A[BB * G4];
__device__ float d_E[2 * G4];
__device__ float d_h0[BB * FF];
__device__ float d_c0[BB * FF];
__device__ __half d_Y16[(size_t)BB * LL * FF];   // h stream, [b][t][f] f16

__device__ __forceinline__ unsigned smem_u32(const void* p) {
    unsigned a;
    asm("{ .reg .u64 t; cvta.to.shared.u64 t, %1; cvt.u32.u64 %0, t; }"
        : "=r"(a) : "l"(p));
    return a;
}
__device__ __forceinline__ float tanh_mufu(float x) {
    float y; asm("tanh.approx.f32 %0, %1;" : "=f"(y) : "f"(x)); return y;
}
__device__ __forceinline__ unsigned packh2(float lo, float hi) {
    __half2 h = __floats2half2_rn(lo, hi);
    return *(unsigned*)&h;
}
__device__ __forceinline__ void mma16816(float* d, const unsigned* a, const unsigned* b) {
    asm("mma.sync.aligned.m16n8k16.row.col.f32.f16.f16.f32 "
        "{%0,%1,%2,%3}, {%4,%5,%6,%7}, {%8,%9}, {%0,%1,%2,%3};"
        : "+f"(d[0]), "+f"(d[1]), "+f"(d[2]), "+f"(d[3])
        : "r"(a[0]), "r"(a[1]), "r"(a[2]), "r"(a[3]), "r"(b[0]), "r"(b[1]));
}
__device__ __forceinline__ void ldsm4(unsigned* r, unsigned addr) {
    asm volatile("ldmatrix.sync.aligned.m8n8.x4.shared.b16 {%0,%1,%2,%3}, [%4];"
        : "=r"(r[0]), "=r"(r[1]), "=r"(r[2]), "=r"(r[3]) : "r"(addr));
}

// ---------------------------------------------------------------------------
// Kernel 1: precompute A[b], E[k], h0[b], c0[b]  (proven; clock canary 19.5us)
// ---------------------------------------------------------------------------
__global__ void precompute_kernel(
    const float* __restrict__ g,
    const float* __restrict__ W_emb,  const float* __restrict__ b_emb,
    const float* __restrict__ W_g1,   const float* __restrict__ b_g1,
    const float* __restrict__ W_g2,   const float* __restrict__ b_g2,
    const float* __restrict__ W_gh,   const float* __restrict__ b_gh,
    const float* __restrict__ W_gc,   const float* __restrict__ b_gc,
    const float* __restrict__ Wi,     const float* __restrict__ b_lstm)
{
    int b = blockIdx.x;
    int j = threadIdx.x;
    __shared__ float sh_t[HH];
    __shared__ float sh_gv[FF];

    float gb = g[b];
    if (j < HH) sh_t[j] = tanhf(gb * W_g1[j] + b_g1[j]);
    __syncthreads();
    if (j < FF) {
        float acc = b_g2[j];
        #pragma unroll 8
        for (int h = 0; h < HH; h++) acc += sh_t[h] * W_g2[h * FF + j];
        sh_gv[j] = acc;
        d_h0[b * FF + j] = gb * W_gh[j] + b_gh[j];
        d_c0[b * FF + j] = gb * W_gc[j] + b_gc[j];
    }
    __syncthreads();
    float acc = b_lstm[j];
    #pragma unroll 8
    for (int f = 0; f < FF; f++) acc += (b_emb[f] + sh_gv[f]) * Wi[f * G4 + j];
    d_A[b * G4 + j] = acc;

    if (b == 0) {
        float e0 = 0.f, e1 = 0.f;
        #pragma unroll 8
        for (int f = 0; f < FF; f++) {
            float wi = Wi[f * G4 + j];
            e0 += W_emb[f] * wi;
            e1 += W_emb[FF + f] * wi;
        }
        d_E[j] = e0;
        d_E[G4 + j] = e1;
    }
}

// ---------------------------------------------------------------------------
// Kernel 2: HMMA LSTM. One CTA = 16 batches, 256 threads (8 warps).
// Per step: D[16x256] = h[16x64] @ Wh via mma.sync.m16n8k16.
//   warp w owns cols [32w, 32w+32) = 4 n-tiles; gate = w>>1 (uniform act).
//   A (h, f16) in SMEM hS[16][72], loaded via ldmatrix.x4 per k-chunk.
//   B (Wh) fragments constant in registers (32 regs/lane).
// Epilogue: act -> actS[16][260], sync, c-update per (batch, 4 feats),
// h -> f16 -> hS + d_Y16 stream, sync.
// ---------------------------------------------------------------------------
__global__ void __launch_bounds__(256) lstm_mma_kernel(
    const int*   __restrict__ s,      // (B, L)
    const float* __restrict__ Wh)     // (64, 256)
{
    __shared__ __align__(16) __half hS[16][72];      // h, 72-half pitch
    __shared__ __align__(16) float actS[16][260];    // activated gates
    __shared__ unsigned tokm[LL];

    int tid  = threadIdx.x;
    int wid  = tid >> 5;
    int lane = tid & 31;
    int g    = lane >> 2;      // groupID 0..7
    int tg   = lane & 3;       // thread-in-group
    int bg0  = blockIdx.x * GB;
    int colbase = 32 * wid;

    // ---- constant B fragments: Br[t][kk][0..1] ----
    unsigned Br[4][4][2];
    {
        int n = colbase + g;   // + 8t added below
        #pragma unroll
        for (int t = 0; t < 4; t++)
            #pragma unroll
            for (int kk = 0; kk < 4; kk++) {
                int k0 = 16 * kk + 2 * tg;
                int nn = n + 8 * t;
                Br[t][kk][0] = packh2(Wh[k0 * G4 + nn], Wh[(k0 + 1) * G4 + nn]);
                Br[t][kk][1] = packh2(Wh[(k0 + 8) * G4 + nn], Wh[(k0 + 9) * G4 + nn]);
            }
    }

    // ---- per-lane x-bias: D lane covers batches {g, g+8}, cols {c0, c0+1} ----
    float xbA[4][2], xbB[4][2], xd[4][2];
    #pragma unroll
    for (int t = 0; t < 4; t++) {
        int c0 = colbase + 8 * t + 2 * tg;
        #pragma unroll
        for (int j = 0; j < 2; j++) {
            float e0 = d_E[c0 + j];
            xbA[t][j] = d_A[(bg0 + g) * G4 + c0 + j] + e0;
            xbB[t][j] = d_A[(bg0 + g + 8) * G4 + c0 + j] + e0;
            xd[t][j]  = d_E[G4 + c0 + j] - e0;
        }
    }

    // uniform activation constants per warp: gate = wid>>1 (2 = tanh)
    int gate = wid >> 1;
    float aA = (gate == 2) ? 1.f : 0.5f;
    float aB = aA;
    float aC = (gate == 2) ? 0.f : 0.5f;

    // token masks: bit b of tokm[u] = s[bg0+b][u] & 1
    {
        unsigned m = 0;
        #pragma unroll
        for (int b = 0; b < GB; b++)
            m |= ((unsigned)s[(bg0 + b) * LL + tid] & 1u) << b;
        tokm[tid] = m;
    }

    // c state + h0 -> hS (thread owns (b2, f2..f2+3))
    int b2 = tid >> 4;
    int f2 = (tid & 15) << 2;
    float c[4];
    #pragma unroll
    for (int j = 0; j < 4; j++) c[j] = d_c0[(bg0 + b2) * FF + f2 + j];
    {
        unsigned h01 = packh2(d_h0[(bg0 + b2) * FF + f2 + 0],
                              d_h0[(bg0 + b2) * FF + f2 + 1]);
        unsigned h23 = packh2(d_h0[(bg0 + b2) * FF + f2 + 2],
                              d_h0[(bg0 + b2) * FF + f2 + 3]);
        *(uint2*)&hS[b2][f2] = make_uint2(h01, h23);
    }
    // ldmatrix per-lane row address (row = lane&15, col-half = lane>>4)
    unsigned lm_base = smem_u32(&hS[0][0])
                     + ((lane & 15) * 72 + (lane >> 4) * 8) * 2;
    __syncthreads();

    #pragma unroll 1
    for (int u = 0; u < LL; u++) {
        // A fragments for the 4 k-chunks
        unsigned Af[4][4];
        #pragma unroll
        for (int kk = 0; kk < 4; kk++) ldsm4(Af[kk], lm_base + 32 * kk);

        float acc[4][4];
        #pragma unroll
        for (int t = 0; t < 4; t++)
            #pragma unroll
            for (int j = 0; j < 4; j++) acc[t][j] = 0.f;
        #pragma unroll
        for (int kk = 0; kk < 4; kk++)
            #pragma unroll
            for (int t = 0; t < 4; t++)
                mma16816(acc[t], Af[kk], Br[t][kk]);

        // z = D + x (+ token delta), activate, publish
        unsigned mk = u ? tokm[u - 1] : 0u;
        float s0 = (float)((mk >> g) & 1u);
        float s1 = (float)((mk >> (g + 8)) & 1u);
        #pragma unroll
        for (int t = 0; t < 4; t++) {
            int c0 = colbase + 8 * t + 2 * tg;
            float zA0 = acc[t][0] + fmaf(s0, xd[t][0], xbA[t][0]);
            float zA1 = acc[t][1] + fmaf(s0, xd[t][1], xbA[t][1]);
            float zB0 = acc[t][2] + fmaf(s1, xd[t][0], xbB[t][0]);
            float zB1 = acc[t][3] + fmaf(s1, xd[t][1], xbB[t][1]);
            float2 aAv = make_float2(fmaf(tanh_mufu(aA * zA0), aB, aC),
                                     fmaf(tanh_mufu(aA * zA1), aB, aC));
            float2 aBv = make_float2(fmaf(tanh_mufu(aA * zB0), aB, aC),
                                     fmaf(tanh_mufu(aA * zB1), aB, aC));
            *(float2*)&actS[g][c0]     = aAv;
            *(float2*)&actS[g + 8][c0] = aBv;
        }
        __syncthreads();

        // c/h update for (b2, f2..f2+3)
        float4 ai = *(float4*)&actS[b2][f2];
        float4 af = *(float4*)&actS[b2][FF + f2];
        float4 ag = *(float4*)&actS[b2][2 * FF + f2];
        float4 ao = *(float4*)&actS[b2][3 * FF + f2];
        float h[4];
        c[0] = af.x * c[0] + ai.x * ag.x;  h[0] = ao.x * tanh_mufu(c[0]);
        c[1] = af.y * c[1] + ai.y * ag.y;  h[1] = ao.y * tanh_mufu(c[1]);
        c[2] = af.z * c[2] + ai.z * ag.z;  h[2] = ao.z * tanh_mufu(c[2]);
        c[3] = af.w * c[3] + ai.w * ag.w;  h[3] = ao.w * tanh_mufu(c[3]);

        unsigned h01 = packh2(h[0], h[1]);
        unsigned h23 = packh2(h[2], h[3]);
        *(uint2*)&hS[b2][f2] = make_uint2(h01, h23);
        *(uint2*)&d_Y16[((size_t)(bg0 + b2) * LL + u) * FF + f2] =
            make_uint2(h01, h23);
        __syncthreads();
    }
}

// ---------------------------------------------------------------------------
// Kernel 3: epilogue — logits from f16 h, log-softmax, per-batch sum.
// grid = B, block = 256 (thread t owns timestep t). d_Y16 layout [b][t][f].
// ---------------------------------------------------------------------------
__global__ void __launch_bounds__(256) logit_kernel(
    const int*   __restrict__ s,      // (B, L)
    const float* __restrict__ W_amp,  // (64, 2)
    const float* __restrict__ b_amp,  // (2)
    float* __restrict__ out)          // (B,)
{
    int b = blockIdx.x;
    int t = threadIdx.x;
    int lane = t & 31;
    int warp = t >> 5;

    __shared__ __align__(16) float sw[2 * FF];
    __shared__ float red[8];
    if (t < 2 * FF) sw[t] = W_amp[t];
    __syncthreads();

    const uint4* y4 = (const uint4*)(d_Y16 + ((size_t)b * LL + t) * FF);
    float l0 = b_amp[0], l1 = b_amp[1];
    #pragma unroll
    for (int i = 0; i < 8; i++) {
        uint4 v = y4[i];
        unsigned ww[4] = {v.x, v.y, v.z, v.w};
        #pragma unroll
        for (int j = 0; j < 4; j++) {
            float2 f2v = __half22float2(*(__half2*)&ww[j]);
            int f = i * 8 + 2 * j;
            l0 += f2v.x * sw[2 * f + 0] + f2v.y * sw[2 * f + 2];
            l1 += f2v.x * sw[2 * f + 1] + f2v.y * sw[2 * f + 3];
        }
    }
    int tok = s[b * LL + t];
    float m = fmaxf(l0, l1);
    float lse = m + __logf(__expf(l0 - m) + __expf(l1 - m));
    float lp = (tok ? l1 : l0) - lse;

    #pragma unroll
    for (int o = 16; o > 0; o >>= 1)
        lp += __shfl_down_sync(0xffffffffu, lp, o);
    if (lane == 0) red[warp] = lp;
    __syncthreads();
    if (warp == 0) {
        float v = (lane < 8) ? red[lane] : 0.f;
        #pragma unroll
        for (int o = 4; o > 0; o >>= 1)
            v += __shfl_down_sync(0xffffffffu, v, o);
        if (lane == 0) out[b] = v;
    }
}

// ---------------------------------------------------------------------------
// Launch. Input order:
// 0:s 1:g 2:W_emb 3:b_emb 4:W_g1 5:b_g1 6:W_g2 7:b_g2 8:W_gh 9:b_gh
// 10:W_gc 11:b_gc 12:Wi 13:Wh 14:b_lstm 15:W_amp 16:b_amp
// ---------------------------------------------------------------------------
extern "C" void kernel_launch(void* const* d_in, const int* in_sizes, int n_in,
                              void* d_out, int out_size) {
    const int*   s      = (const int*)  d_in[0];
    const float* g      = (const float*)d_in[1];
    const float* W_emb  = (const float*)d_in[2];
    const float* b_emb  = (const float*)d_in[3];
    const float* W_g1   = (const float*)d_in[4];
    const float* b_g1   = (const float*)d_in[5];
    const float* W_g2   = (const float*)d_in[6];
    const float* b_g2   = (const float*)d_in[7];
    const float* W_gh   = (const float*)d_in[8];
    const float* b_gh   = (const float*)d_in[9];
    const float* W_gc   = (const float*)d_in[10];
    const float* b_gc   = (const float*)d_in[11];
    const float* Wi     = (const float*)d_in[12];
    const float* Wh     = (const float*)d_in[13];
    const float* b_lstm = (const float*)d_in[14];
    const float* W_amp  = (const float*)d_in[15];
    const float* b_amp  = (const float*)d_in[16];
    float* out = (float*)d_out;

    precompute_kernel<<<BB, 256>>>(g, W_emb, b_emb, W_g1, b_g1, W_g2, b_g2,
                                   W_gh, b_gh, W_gc, b_gc, Wi, b_lstm);
    lstm_mma_kernel<<<BB / GB, 256>>>(s, Wh);
    logit_kernel<<<BB, 256>>>(s, W_amp, b_amp, out);
}